// round 13
// baseline (speedup 1.0000x reference)
#include <cuda_runtime.h>
#include <math_constants.h>
#include <math.h>

#define BSZ 4
#define NP  2048
#define EPSF 1e-6f
#define INF  CUDART_INF_F

typedef unsigned long long u64;

// ---------------- scratch ----------------
__device__ float4 g_pk[2][BSZ][NP / 2];   // sorted pairs (-x0,-x1,-y0,-y1)
__device__ float2 g_xy[2][BSZ][NP];       // sorted (x,y)
__device__ float g_knn[2][BSZ][NP * 3];   // sqrt'd 3NN (incl self)
__device__ float g_sel[14][14];
__device__ float g_hex_partial[1024];
__device__ float g_feas_partial[128];
__device__ float g_sumr[BSZ];
__device__ int   g_done;                  // reset by pairs_kernel each launch

// ---------------- packed f32x2 helpers ----------------
__device__ __forceinline__ u64 addx2(u64 a, u64 b) {
    u64 r; asm("add.rn.f32x2 %0,%1,%2;" : "=l"(r) : "l"(a), "l"(b)); return r; }
__device__ __forceinline__ u64 mulx2(u64 a, u64 b) {
    u64 r; asm("mul.rn.f32x2 %0,%1,%2;" : "=l"(r) : "l"(a), "l"(b)); return r; }
__device__ __forceinline__ u64 fmax2_(u64 a, u64 b, u64 c) {
    u64 r; asm("fma.rn.f32x2 %0,%1,%2,%3;" : "=l"(r) : "l"(a), "l"(b), "l"(c)); return r; }
__device__ __forceinline__ u64 dup2(float v) {
    u64 r; asm("mov.b64 %0,{%1,%1};" : "=l"(r) : "f"(v)); return r; }
__device__ __forceinline__ u64 pk2(float a, float b) {
    u64 r; asm("mov.b64 %0,{%1,%2};" : "=l"(r) : "f"(a), "f"(b)); return r; }
__device__ __forceinline__ float2 upk(u64 v) {
    float2 r; asm("mov.b64 {%0,%1},%2;" : "=f"(r.x), "=f"(r.y) : "l"(v)); return r; }

// ---------------- sortable key ----------------
__device__ __forceinline__ unsigned fkey(float f) {
    unsigned u = __float_as_uint(f);
    return (u & 0x80000000u) ? ~u : (u | 0x80000000u);
}
__device__ __forceinline__ float unfkey(unsigned k) {
    unsigned u = (k & 0x80000000u) ? (k ^ 0x80000000u) : ~k;
    return __uint_as_float(u);
}

// ---------------- branch-free sorted inserts ----------------
#define INS3(a0,a1,a2,d) do{ \
    float _m1 = fmaxf(a0,(d)), _m2 = fmaxf(a1,(d)); \
    a0 = fminf(a0,(d)); a1 = fminf(a1,_m1); a2 = fminf(a2,_m2); }while(0)

#define INS5(a0,a1,a2,a3,a4,d) do{ \
    float _m1 = fmaxf(a0,(d)), _m2 = fmaxf(a1,(d)), _m3 = fmaxf(a2,(d)), _m4 = fmaxf(a3,(d)); \
    a0 = fminf(a0,(d)); a1 = fminf(a1,_m1); a2 = fminf(a2,_m2); \
    a3 = fminf(a3,_m3); a4 = fminf(a4,_m4); }while(0)

// ---------------- warp k-min extraction ----------------
__device__ __forceinline__ float pop3(float& a0, float& a1, float& a2, int lane) {
    float bv = a0; int bl = lane;
#pragma unroll
    for (int off = 16; off; off >>= 1) {
        float ov = __shfl_down_sync(0xffffffffu, bv, off);
        int   ol = __shfl_down_sync(0xffffffffu, bl, off);
        if (ov < bv) { bv = ov; bl = ol; }
    }
    bv = __shfl_sync(0xffffffffu, bv, 0);
    bl = __shfl_sync(0xffffffffu, bl, 0);
    if (lane == bl) { a0 = a1; a1 = a2; a2 = INF; }
    return bv;
}
__device__ __forceinline__ float pop5(float& a0, float& a1, float& a2, float& a3, float& a4,
                                      int lane) {
    float bv = a0; int bl = lane;
#pragma unroll
    for (int off = 16; off; off >>= 1) {
        float ov = __shfl_down_sync(0xffffffffu, bv, off);
        int   ol = __shfl_down_sync(0xffffffffu, bl, off);
        if (ov < bv) { bv = ov; bl = ol; }
    }
    bv = __shfl_sync(0xffffffffu, bv, 0);
    bl = __shfl_sync(0xffffffffu, bl, 0);
    if (lane == bl) { a0 = a1; a1 = a2; a2 = a3; a3 = a4; a4 = INF; }
    return bv;
}

// ---------------- windowed scans ----------------
__device__ __forceinline__ void scan5(const float4* __restrict__ PK, int plo, int iters,
                                      u64 qx2, u64 qy2, int lane,
                                      float& a0, float& a1, float& a2, float& a3, float& a4) {
    a0 = INF; a1 = INF; a2 = INF; a3 = INF; a4 = INF;
#pragma unroll 4
    for (int it = 0; it < iters; it++) {
        float4 vf = __ldg(&PK[plo + lane + it * 32]);
        u64 vx = pk2(vf.x, vf.y), vy = pk2(vf.z, vf.w);
        u64 dxx = addx2(qx2, vx);
        u64 dyy = addx2(qy2, vy);
        float2 d = upk(fmax2_(dyy, dyy, mulx2(dxx, dxx)));
        INS5(a0, a1, a2, a3, a4, d.x);
        INS5(a0, a1, a2, a3, a4, d.y);
    }
}
__device__ __forceinline__ void scan3(const float4* __restrict__ PK, int plo, int iters,
                                      u64 qx2, u64 qy2, int lane,
                                      float& a0, float& a1, float& a2) {
    a0 = INF; a1 = INF; a2 = INF;
#pragma unroll 4
    for (int it = 0; it < iters; it++) {
        float4 vf = __ldg(&PK[plo + lane + it * 32]);
        u64 vx = pk2(vf.x, vf.y), vy = pk2(vf.z, vf.w);
        u64 dxx = addx2(qx2, vx);
        u64 dyy = addx2(qy2, vy);
        float2 d = upk(fmax2_(dyy, dyy, mulx2(dxx, dxx)));
        INS3(a0, a1, a2, d.x);
        INS3(a0, a1, a2, d.y);
    }
}
// clamped window start (points), even
__device__ __forceinline__ int winlo(int i, int hw) {
    int lo = i - hw;
    lo = lo < 0 ? 0 : lo;
    int mx = NP - 2 * hw;
    lo = lo > mx ? mx : lo;
    return lo & ~1;
}
__device__ __forceinline__ float wingap(const float2* __restrict__ XY, float qx,
                                        int lo, int hw) {
    float gl = lo > 0 ? qx - XY[lo - 1].x : INF;
    float gr = (lo + 2 * hw) < NP ? XY[lo + 2 * hw].x - qx : INF;
    return fminf(gl, gr);
}

// ---------------- hex contribution ----------------
__device__ __forceinline__ void hex_contrib(float dx, float dy, float d2,
                                            float kth, float inv_sigma,
                                            float& wsum, float& wre, float& wim) {
    float d2e = d2 + EPSF;
    float dist = d2e * rsqrtf(d2e);
    float arg = (kth - dist) * inv_sigma;
    float e = __expf(-arg);
    float w = __fdividef(1.0f, 1.0f + e);
    float c = dx;
    if (fabsf(c) < EPSF) c = c + EPSF;
    float n2 = fmaf(c, c, dy * dy);
    float inv = __fdividef(1.0f, n2);
    float un = (c * c - dy * dy) * inv;
    float vn = (2.0f * c * dy) * inv;
    float re4 = un * un - vn * vn;
    float im4 = 2.0f * un * vn;
    wsum += w;
    wre = fmaf(w, re4, wre);
    wim = fmaf(w, im4, wim);
}

// ---------------- radix-select core (shared-memory layout via raw buffer) -----------
#define SEL_BYTES 41232
__device__ void select_core(char* sm, const float* __restrict__ src, int mode,
                            int r, int a, int slot) {
    unsigned* skeys = (unsigned*)sm;           // 8192 * 4 = 32768
    int* hist = (int*)(sm + 32768);            // 2048 * 4 = 8192
    int* wtot = (int*)(sm + 40960);            // 32 * 4
    int* woff = (int*)(sm + 41088);            // 32 * 4
    unsigned* s_bin = (unsigned*)(sm + 41216);
    int* s_rank = (int*)(sm + 41220);
    int tid = threadIdx.x, lane = tid & 31, wid = tid >> 5;

    if (mode == 0) {
#pragma unroll
        for (int it = 0; it < 8; it++) {
            int idx = tid + it * 1024;
            skeys[idx] = fkey(src[idx * 3]);
        }
    } else {
#pragma unroll
        for (int it = 0; it < 8; it++) {
            int idx = tid + it * 1024;
            skeys[idx] = (idx < NP * 3) ? fkey(src[idx]) : 0xFFFFFFFFu;
        }
    }
    __syncthreads();

    unsigned prefix = 0;
#pragma unroll
    for (int level = 0; level < 3; level++) {
        int nb = (level < 2) ? 2048 : 1024;
        int shift = (level == 0) ? 21 : (level == 1 ? 10 : 0);
        for (int bI = tid; bI < nb; bI += 1024) hist[bI] = 0;
        __syncthreads();
#pragma unroll
        for (int it = 0; it < 8; it++) {
            unsigned k = skeys[tid + it * 1024];
            bool ok = (level == 0) ||
                      (level == 1 ? ((k >> 21) == prefix) : ((k >> 10) == prefix));
            unsigned act = __ballot_sync(0xffffffffu, ok);
            if (ok) {
                unsigned bin = (k >> shift) & (nb - 1);
                unsigned grp = __match_any_sync(act, bin);
                int ldr = __ffs(grp) - 1;
                if (lane == ldr) atomicAdd(&hist[bin], __popc(grp));
            }
        }
        __syncthreads();
        int per = nb >> 10;
        int base = tid * per;
        int local = 0;
        for (int bI = 0; bI < per; bI++) local += hist[base + bI];
        int incl = local;
#pragma unroll
        for (int off = 1; off < 32; off <<= 1) {
            int v = __shfl_up_sync(0xffffffffu, incl, off);
            if (lane >= off) incl += v;
        }
        if (lane == 31) wtot[wid] = incl;
        __syncthreads();
        if (tid < 32) {
            int v = wtot[tid];
            int inc2 = v;
#pragma unroll
            for (int off = 1; off < 32; off <<= 1) {
                int u = __shfl_up_sync(0xffffffffu, inc2, off);
                if (tid >= off) inc2 += u;
            }
            woff[tid] = inc2 - v;
        }
        __syncthreads();
        int myExcl = woff[wid] + incl - local;
        if (r >= myExcl && r < myExcl + local) {
            int rr2 = r - myExcl;
            for (int bI = 0; bI < per; bI++) {
                int h = hist[base + bI];
                if (rr2 < h) { *s_bin = base + bI; *s_rank = rr2; break; }
                rr2 -= h;
            }
        }
        __syncthreads();
        prefix = (prefix << ((level == 2) ? 10 : 11)) | *s_bin;
        r = *s_rank;
        __syncthreads();
    }
    if (tid == 0)
        g_sel[a][slot] = unfkey(prefix);
}

// ---------------- channel-select tables (68 tasks) ----------------
#define XY10 409,410,2047,2048,4095,4096,6143,6144,7781,7782
#define Z14  409,410,819,820,2047,2048,4095,4096,6143,6144,7371,7372,7781,7782
#define R10(x) x,x,x,x,x,x,x,x,x,x
#define R14(x) x,x,x,x,x,x,x,x,x,x,x,x,x,x
#define S10 0,1,2,3,4,5,6,7,8,9
#define S14 0,1,2,3,4,5,6,7,8,9,10,11,12,13

__constant__ unsigned char  ch_arr[68]  = { R10(0), R10(1), R14(2), R10(3), R10(4), R14(5) };
__constant__ unsigned short ch_rank[68] = { XY10, XY10, Z14, XY10, XY10, Z14 };
__constant__ unsigned char  ch_slot[68] = { S10, S10, S14, S10, S10, S14 };

// ---------------- knn-select tables (32 tasks) ----------------
#define K4   3071,3072,5835,5836
#define R4(x)  x,x,x,x
#define S4  2,3,4,5
__constant__ unsigned char  kn_arr[32]  = { R4(0),R4(1),R4(2),R4(3),R4(4),R4(5),R4(6),R4(7) };
__constant__ unsigned short kn_rank[32] = { K4,K4,K4,K4,K4,K4,K4,K4 };
__constant__ unsigned char  kn_slot[32] = { S4,S4,S4,S4,S4,S4,S4,S4 };

// ================ prep: [0,8) sort; [8,136) feasibility; [136,204) channel select ====
__global__ void __launch_bounds__(1024) prep_kernel(const float* __restrict__ real_in,
                                                    const float* __restrict__ fake_in) {
    __shared__ __align__(16) char sm[SEL_BYTES];
    int bx = blockIdx.x, tid = threadIdx.x;

    if (bx < 8) {
        // -------- register bitonic sort by x --------
        unsigned* skey = (unsigned*)sm;          // 8KB
        float* sy = (float*)(sm + 8192);         // 8KB
        int t = bx >> 2, b = bx & 3;
        const float* base = (t ? fake_in : real_in) + b * NP * 3;
        int e0 = 2 * tid, e1 = e0 + 1;
        unsigned k0 = fkey(base[e0 * 3]); float y0 = base[e0 * 3 + 1];
        unsigned k1 = fkey(base[e1 * 3]); float y1 = base[e1 * 3 + 1];
        for (int k = 2; k <= NP; k <<= 1) {
            bool up = ((e0 & k) == 0);
            for (int j = k >> 1; j >= 64; j >>= 1) {
                skey[e0] = k0; sy[e0] = y0;
                skey[e1] = k1; sy[e1] = y1;
                __syncthreads();
                unsigned p0 = skey[e0 ^ j]; float q0 = sy[e0 ^ j];
                unsigned p1 = skey[e1 ^ j]; float q1 = sy[e1 ^ j];
                bool tm0 = (((e0 & j) == 0) == up);
                if (tm0 ? (p0 < k0) : (p0 > k0)) { k0 = p0; y0 = q0; }
                bool tm1 = (((e1 & j) == 0) == up);
                if (tm1 ? (p1 < k1) : (p1 > k1)) { k1 = p1; y1 = q1; }
                __syncthreads();
            }
            int jmax = (k >> 1) < 32 ? (k >> 1) : 32;
            for (int j = jmax; j >= 2; j >>= 1) {
                unsigned p0 = __shfl_xor_sync(0xffffffffu, k0, j >> 1);
                float    q0 = __shfl_xor_sync(0xffffffffu, y0, j >> 1);
                unsigned p1 = __shfl_xor_sync(0xffffffffu, k1, j >> 1);
                float    q1 = __shfl_xor_sync(0xffffffffu, y1, j >> 1);
                bool tm = (((e0 & j) == 0) == up);
                if (tm ? (p0 < k0) : (p0 > k0)) { k0 = p0; y0 = q0; }
                if (tm ? (p1 < k1) : (p1 > k1)) { k1 = p1; y1 = q1; }
            }
            if (up ? (k1 < k0) : (k1 > k0)) {
                unsigned tk = k0; k0 = k1; k1 = tk;
                float ty = y0; y0 = y1; y1 = ty;
            }
        }
        float x0 = unfkey(k0), x1 = unfkey(k1);
        g_xy[t][b][e0] = make_float2(x0, y0);
        g_xy[t][b][e1] = make_float2(x1, y1);
        g_pk[t][b][tid] = make_float4(-x0, -x1, -y0, -y1);
    } else if (bx < 136) {
        // -------- feasibility: dense strict lower triangle, 32 warps x 2 rows --------
        float4* spk4 = (float4*)sm;              // 16KB
        u64* srrp = (u64*)(sm + 16384);          // 8KB
        float* s_acc = (float*)(sm + 24576);     // 128B
        float* s_red = (float*)(sm + 24704);     // 4KB
        int bx2 = bx - 8;
        int b = bx2 >> 5, kk = bx2 & 31;
        int warp = tid >> 5, lane = tid & 31;
        const float* base = fake_in + b * NP * 3;
        {
            const float* p0 = base + 6 * tid;
            spk4[tid] = make_float4(-p0[0], -p0[3], -p0[1], -p0[4]);
            srrp[tid] = pk2(fabsf(p0[2]), fabsf(p0[5]));
        }
        __syncthreads();
        if (kk == 0) {
            float2 rr = upk(srrp[tid]);
            s_red[tid] = rr.x + rr.y;
            __syncthreads();
            for (int off = 512; off; off >>= 1) {
                if (tid < off) s_red[tid] += s_red[tid + off];
                __syncthreads();
            }
            if (tid == 0) g_sumr[b] = s_red[0];
        }
        int i0 = kk * 64 + warp * 2;
        u64 qx2[2], qy2[2], ri2[2];
#pragma unroll
        for (int p = 0; p < 2; p++) {
            qx2[p] = dup2(base[(i0 + p) * 3]);
            qy2[p] = dup2(base[(i0 + p) * 3 + 1]);
            ri2[p] = dup2(fabsf(base[(i0 + p) * 3 + 2]) - 1e-4f);
        }
        float acc = 0.0f;
        for (int jp = lane; 2 * jp <= i0; jp += 32) {
            float4 vf = spk4[jp];
            u64 vx = pk2(vf.x, vf.y), vy = pk2(vf.z, vf.w);
            u64 rrv = srrp[jp];
            int idx0 = 2 * jp, idx1 = idx0 + 1;
#pragma unroll
            for (int p = 0; p < 2; p++) {
                u64 dxx = addx2(qx2[p], vx);
                u64 dyy = addx2(qy2[p], vy);
                float2 sq = upk(fmax2_(dyy, dyy, mulx2(dxx, dxx)));
                u64 thr = addx2(ri2[p], rrv);
                float2 th = upk(thr);
                float2 t2 = upk(mulx2(thr, thr));
                if (idx0 < i0 + p && sq.x > 0.0f && th.x > 0.0f && sq.x < t2.x)
                    acc += th.x - sq.x * rsqrtf(sq.x);
                if (idx1 < i0 + p && sq.y > 0.0f && th.y > 0.0f && sq.y < t2.y)
                    acc += th.y - sq.y * rsqrtf(sq.y);
            }
        }
#pragma unroll
        for (int off = 16; off; off >>= 1)
            acc += __shfl_down_sync(0xffffffffu, acc, off);
        if (lane == 0) s_acc[warp] = acc;
        __syncthreads();
        if (tid == 0) {
            float s = 0.0f;
            for (int w = 0; w < 32; w++) s += s_acc[w];
            g_feas_partial[bx2] = s;
        }
    } else {
        // -------- channel selects (don't depend on pairs) --------
        int task = bx - 136;
        int a = ch_arr[task];
        const float* src = (a < 3 ? real_in : fake_in) + (a % 3);
        select_core(sm, src, 0, ch_rank[task], a, ch_slot[task]);
    }
}

// ================ pairs: [0,1024) fake hex; [1024,2048) real kNN — 1 q/warp =========
__global__ void __launch_bounds__(256) pairs_kernel() {
    __shared__ float s_acc[8];
    int bx = blockIdx.x, tid = threadIdx.x;
    int warp = tid >> 5, lane = tid & 31;
    if (bx == 0 && tid == 0) g_done = 0;      // reset spin counter for next kernel

    if (bx < 1024) {
        // -------- fake: fused kNN + hex, 3-tier windows --------
        int b = bx >> 8, kk = bx & 255;
        int i = kk * 8 + warp;
        const float4* __restrict__ PK = &g_pk[1][b][0];
        const float2* __restrict__ XY = &g_xy[1][b][0];
        float2 q = XY[i];
        u64 qx2 = dup2(q.x), qy2 = dup2(q.y);
        float a0, a1, a2, a3, a4;

        // tier 1: halfwidth 128
        int lo = winlo(i, 128);
        scan5(PK, lo >> 1, 4, qx2, qy2, lane, a0, a1, a2, a3, a4);
        float o0 = pop5(a0, a1, a2, a3, a4, lane);
        float o1 = pop5(a0, a1, a2, a3, a4, lane);
        float o2 = pop5(a0, a1, a2, a3, a4, lane);
        float o3 = pop5(a0, a1, a2, a3, a4, lane); (void)o3;
        float o4 = pop5(a0, a1, a2, a3, a4, lane);
        float g = wingap(XY, q.x, lo, 128);
        if (g * g < o4) {
            // tier 2: halfwidth 512
            lo = winlo(i, 512);
            scan5(PK, lo >> 1, 16, qx2, qy2, lane, a0, a1, a2, a3, a4);
            o0 = pop5(a0, a1, a2, a3, a4, lane);
            o1 = pop5(a0, a1, a2, a3, a4, lane);
            o2 = pop5(a0, a1, a2, a3, a4, lane);
            o3 = pop5(a0, a1, a2, a3, a4, lane); (void)o3;
            o4 = pop5(a0, a1, a2, a3, a4, lane);
            g = wingap(XY, q.x, lo, 512);
            if (g * g < o4) {
                // tier 3: dense
                scan5(PK, 0, 32, qx2, qy2, lane, a0, a1, a2, a3, a4);
                o0 = pop5(a0, a1, a2, a3, a4, lane);
                o1 = pop5(a0, a1, a2, a3, a4, lane);
                o2 = pop5(a0, a1, a2, a3, a4, lane);
                o3 = pop5(a0, a1, a2, a3, a4, lane); (void)o3;
                o4 = pop5(a0, a1, a2, a3, a4, lane);
            }
        }
        if (lane == 0) {   // kNN incl self: o0=0(self), o1, o2
            float* dst = &g_knn[1][b][i * 3];
            dst[0] = sqrtf(o0 + EPSF); dst[1] = sqrtf(o1 + EPSF); dst[2] = sqrtf(o2 + EPSF);
        }
        float kth = sqrtf(o4 + EPSF);
        float sg = fmaxf(0.1f * fmaxf(kth, EPSF), EPSF);
        float isg = __fdividef(1.0f, sg);
        float lim = kth + 18.0f * sg;      // beyond: w <= sigmoid(-18), negligible
        float lim2 = fmaf(lim, lim, -EPSF);

        // pass 2: windowed weighted sums, precheck then dense
        float ws = 0.0f, wr = 0.0f, wi = 0.0f;
        int lo2 = winlo(i, 256);
        float g2 = wingap(XY, q.x, lo2, 256);
        int plo2, it2;
        if (g2 * g2 >= lim2) { plo2 = lo2 >> 1; it2 = 8; }
        else                 { plo2 = 0;        it2 = 32; }
        for (int it = 0; it < it2; it++) {
            float4 vf = __ldg(&PK[plo2 + lane + it * 32]);
            u64 vx = pk2(vf.x, vf.y), vy = pk2(vf.z, vf.w);
            u64 dxx = addx2(qx2, vx);
            u64 dyy = addx2(qy2, vy);
            float2 d = upk(fmax2_(dyy, dyy, mulx2(dxx, dxx)));
            if (d.x <= lim2) {
                float2 fx = upk(dxx), fy = upk(dyy);
                hex_contrib(fx.x, fy.x, d.x, kth, isg, ws, wr, wi);
            }
            if (d.y <= lim2) {
                float2 fx = upk(dxx), fy = upk(dyy);
                hex_contrib(fx.y, fy.y, d.y, kth, isg, ws, wr, wi);
            }
        }
#pragma unroll
        for (int off = 16; off; off >>= 1) {
            ws += __shfl_down_sync(0xffffffffu, ws, off);
            wr += __shfl_down_sync(0xffffffffu, wr, off);
            wi += __shfl_down_sync(0xffffffffu, wi, off);
        }
        if (lane == 0) {
            float ss = 0.0f, sr = 0.0f, si = 0.0f;   // subtract self exactly once
            hex_contrib(0.0f, 0.0f, 0.0f, kth, isg, ss, sr, si);
            float wsum = ws - ss, wre = wr - sr, wim = wi - si;
            s_acc[warp] = sqrtf(wre * wre + wim * wim) / fmaxf(wsum, EPSF);
        }
        __syncthreads();
        if (tid == 0) {
            float s = 0.0f;
            for (int w = 0; w < 8; w++) s += s_acc[w];
            g_hex_partial[bx] = s;
        }
    } else {
        // -------- real kNN: 3-tier windowed top-3 incl self --------
        int bx2 = bx - 1024;
        int b = bx2 >> 8, kk = bx2 & 255;
        int i = kk * 8 + warp;
        const float4* __restrict__ PK = &g_pk[0][b][0];
        const float2* __restrict__ XY = &g_xy[0][b][0];
        float2 q = XY[i];
        u64 qx2 = dup2(q.x), qy2 = dup2(q.y);
        float a0, a1, a2;

        int lo = winlo(i, 128);
        scan3(PK, lo >> 1, 4, qx2, qy2, lane, a0, a1, a2);
        float o0 = pop3(a0, a1, a2, lane);
        float o1 = pop3(a0, a1, a2, lane);
        float o2 = pop3(a0, a1, a2, lane);
        float g = wingap(XY, q.x, lo, 128);
        if (g * g < o2) {
            lo = winlo(i, 512);
            scan3(PK, lo >> 1, 16, qx2, qy2, lane, a0, a1, a2);
            o0 = pop3(a0, a1, a2, lane);
            o1 = pop3(a0, a1, a2, lane);
            o2 = pop3(a0, a1, a2, lane);
            g = wingap(XY, q.x, lo, 512);
            if (g * g < o2) {
                scan3(PK, 0, 32, qx2, qy2, lane, a0, a1, a2);
                o0 = pop3(a0, a1, a2, lane);
                o1 = pop3(a0, a1, a2, lane);
                o2 = pop3(a0, a1, a2, lane);
            }
        }
        if (lane == 0) {
            float* dst = &g_knn[0][b][i * 3];
            dst[0] = sqrtf(o0 + EPSF); dst[1] = sqrtf(o1 + EPSF); dst[2] = sqrtf(o2 + EPSF);
        }
    }
}

// ---------------- finalize tables (25 nonzero quantile terms) ----------------
__constant__ unsigned char f_ar[25] = {2,2,2,2,2,2,2, 0,0,0,0,0, 1,1,1,1,1,
                                       6,6, 7,7, 8,8, 9,9};
__constant__ unsigned char f_af[25] = {5,5,5,5,5,5,5, 3,3,3,3,3, 4,4,4,4,4,
                                       10,10, 11,11, 12,12, 13,13};
__constant__ unsigned char f_k [25] = {0,1,2,3,4,5,6, 0,1,2,3,4, 0,1,2,3,4,
                                       1,2, 1,2, 1,2, 1,2};
__constant__ double f_q [25] = {0.05,0.1,0.25,0.5,0.75,0.9,0.95,
                                0.05,0.25,0.5,0.75,0.95, 0.05,0.25,0.5,0.75,0.95,
                                0.5,0.95, 0.5,0.95, 0.5,0.95, 0.5,0.95};
__constant__ int    f_n [25] = {8192,8192,8192,8192,8192,8192,8192,
                                8192,8192,8192,8192,8192, 8192,8192,8192,8192,8192,
                                6144,6144, 6144,6144, 6144,6144, 6144,6144};
__constant__ float  f_w [25] = {1.f/7,1.f/7,1.f/7,1.f/7,1.f/7,1.f/7,1.f/7,
                                0.1f,0.1f,0.1f,0.1f,0.1f, 0.1f,0.1f,0.1f,0.1f,0.1f,
                                1.f/12,1.f/12, 1.f/12,1.f/12, 1.f/12,1.f/12, 1.f/12,1.f/12};

// ================ selfin: [0,32) knn selects; block 32 = final (spin-wait) ==========
__global__ void __launch_bounds__(1024) selfin_kernel(const float* __restrict__ fo,
                                                      float* __restrict__ out) {
    __shared__ __align__(16) char sm[SEL_BYTES];
    int bx = blockIdx.x, tid = threadIdx.x;

    if (bx < 32) {
        int a = kn_arr[bx];
        const float* src = &g_knn[0][0][0] + a * (NP * 3);
        select_core(sm, src, 1, kn_rank[bx], 6 + a, kn_slot[bx]);
        if (tid == 0) {
            __threadfence();
            atomicAdd(&g_done, 1);
        }
    } else {
        float* rh = (float*)sm;             // 4KB
        float* rf = (float*)(sm + 4096);    // 4KB
        float* terms = (float*)(sm + 8192); // 100B
        // reductions that don't depend on selects
        rh[tid] = g_hex_partial[tid];
        rf[tid] = (tid < 128) ? g_feas_partial[tid] : 0.0f;
        __syncthreads();
        for (int off = 512; off; off >>= 1) {
            if (tid < off) { rh[tid] += rh[tid + off]; rf[tid] += rf[tid + off]; }
            __syncthreads();
        }
        // wait for the 32 knn-select blocks
        if (tid == 0) {
            while (atomicCAS(&g_done, 32, 32) != 32) { }
            __threadfence();
        }
        __syncthreads();
        if (tid < 25) {
            volatile const float* gs = &g_sel[0][0];
            int ar = f_ar[tid], af = f_af[tid], k = f_k[tid];
            double pos = f_q[tid] * (double)(f_n[tid] - 1);
            int lo = (int)pos;
            float fr = (float)(pos - (double)lo);
            float rlo = gs[ar * 14 + 2 * k], rhi = gs[ar * 14 + 2 * k + 1];
            float flo = gs[af * 14 + 2 * k], fhi = gs[af * 14 + 2 * k + 1];
            float qr = rlo + fr * (rhi - rlo);
            float qf = flo + fr * (fhi - flo);
            float d = qf - qr;
            terms[tid] = f_w[tid] * d * d;
        }
        __syncthreads();
        if (tid == 0) {
            float s_sumr = g_sumr[0] + g_sumr[1] + g_sumr[2] + g_sumr[3];
            float loss = 0.0f;
            for (int i = 0; i < 25; i++) loss += terms[i];
            loss += -rh[0] / (float)(BSZ * NP);             // grid order
            loss += rf[0] / ((float)NP * s_sumr);           // feasibility
            float gg = 0.0f;
            for (int i = 0; i < BSZ; i++) {
                float p = fo[i];
                gg += 0.9f * fmaxf(logf(p), -100.0f) + 0.1f * fmaxf(logf(1.0f - p), -100.0f);
            }
            loss += -gg / (float)BSZ;
            out[0] = loss;
        }
    }
}

// ---------------- launch ----------------
extern "C" void kernel_launch(void* const* d_in, const int* in_sizes, int n_in,
                              void* d_out, int out_size) {
    const float* real_in = (const float*)d_in[0];
    const float* fake_in = (const float*)d_in[1];
    const float* fo      = (const float*)d_in[2];
    float* out = (float*)d_out;

    prep_kernel  <<<204, 1024>>>(real_in, fake_in);
    pairs_kernel <<<2048, 256>>>();
    selfin_kernel<<<33,  1024>>>(fo, out);
}

// round 14
// speedup vs baseline: 1.1002x; 1.1002x over previous
#include <cuda_runtime.h>
#include <math_constants.h>
#include <math.h>

#define BSZ 4
#define NP  2048
#define EPSF 1e-6f
#define INF  CUDART_INF_F

typedef unsigned long long u64;

// ---------------- scratch ----------------
__device__ float4 g_pk[2][BSZ][NP / 2];   // sorted pairs (-x0,-x1,-y0,-y1)
__device__ float2 g_xy[2][BSZ][NP];       // sorted (x,y)
__device__ float g_knn[2][BSZ][NP * 3];   // sqrt'd 3NN (incl self)
__device__ float g_sel[14][14];
__device__ float g_hex_partial[1024];
__device__ float g_feas_partial[128];
__device__ float g_sumr[BSZ];

// ---------------- packed f32x2 helpers ----------------
__device__ __forceinline__ u64 addx2(u64 a, u64 b) {
    u64 r; asm("add.rn.f32x2 %0,%1,%2;" : "=l"(r) : "l"(a), "l"(b)); return r; }
__device__ __forceinline__ u64 mulx2(u64 a, u64 b) {
    u64 r; asm("mul.rn.f32x2 %0,%1,%2;" : "=l"(r) : "l"(a), "l"(b)); return r; }
__device__ __forceinline__ u64 fmax2_(u64 a, u64 b, u64 c) {
    u64 r; asm("fma.rn.f32x2 %0,%1,%2,%3;" : "=l"(r) : "l"(a), "l"(b), "l"(c)); return r; }
__device__ __forceinline__ u64 dup2(float v) {
    u64 r; asm("mov.b64 %0,{%1,%1};" : "=l"(r) : "f"(v)); return r; }
__device__ __forceinline__ u64 pk2(float a, float b) {
    u64 r; asm("mov.b64 %0,{%1,%2};" : "=l"(r) : "f"(a), "f"(b)); return r; }
__device__ __forceinline__ float2 upk(u64 v) {
    float2 r; asm("mov.b64 {%0,%1},%2;" : "=f"(r.x), "=f"(r.y) : "l"(v)); return r; }

// ---------------- sortable key ----------------
__device__ __forceinline__ unsigned fkey(float f) {
    unsigned u = __float_as_uint(f);
    return (u & 0x80000000u) ? ~u : (u | 0x80000000u);
}
__device__ __forceinline__ float unfkey(unsigned k) {
    unsigned u = (k & 0x80000000u) ? (k ^ 0x80000000u) : ~k;
    return __uint_as_float(u);
}

// ---------------- branch-free sorted inserts ----------------
#define INS3(a0,a1,a2,d) do{ \
    float _m1 = fmaxf(a0,(d)), _m2 = fmaxf(a1,(d)); \
    a0 = fminf(a0,(d)); a1 = fminf(a1,_m1); a2 = fminf(a2,_m2); }while(0)

#define INS5(a0,a1,a2,a3,a4,d) do{ \
    float _m1 = fmaxf(a0,(d)), _m2 = fmaxf(a1,(d)), _m3 = fmaxf(a2,(d)), _m4 = fmaxf(a3,(d)); \
    a0 = fminf(a0,(d)); a1 = fminf(a1,_m1); a2 = fminf(a2,_m2); \
    a3 = fminf(a3,_m3); a4 = fminf(a4,_m4); }while(0)

// ---------------- warp k-min extraction ----------------
__device__ __forceinline__ float pop3(float& a0, float& a1, float& a2, int lane) {
    float bv = a0; int bl = lane;
#pragma unroll
    for (int off = 16; off; off >>= 1) {
        float ov = __shfl_down_sync(0xffffffffu, bv, off);
        int   ol = __shfl_down_sync(0xffffffffu, bl, off);
        if (ov < bv) { bv = ov; bl = ol; }
    }
    bv = __shfl_sync(0xffffffffu, bv, 0);
    bl = __shfl_sync(0xffffffffu, bl, 0);
    if (lane == bl) { a0 = a1; a1 = a2; a2 = INF; }
    return bv;
}
__device__ __forceinline__ float pop5(float& a0, float& a1, float& a2, float& a3, float& a4,
                                      int lane) {
    float bv = a0; int bl = lane;
#pragma unroll
    for (int off = 16; off; off >>= 1) {
        float ov = __shfl_down_sync(0xffffffffu, bv, off);
        int   ol = __shfl_down_sync(0xffffffffu, bl, off);
        if (ov < bv) { bv = ov; bl = ol; }
    }
    bv = __shfl_sync(0xffffffffu, bv, 0);
    bl = __shfl_sync(0xffffffffu, bl, 0);
    if (lane == bl) { a0 = a1; a1 = a2; a2 = a3; a3 = a4; a4 = INF; }
    return bv;
}

// ---------------- windowed scans ----------------
__device__ __forceinline__ void scan5(const float4* __restrict__ PK, int plo, int iters,
                                      u64 qx2, u64 qy2, int lane,
                                      float& a0, float& a1, float& a2, float& a3, float& a4) {
    a0 = INF; a1 = INF; a2 = INF; a3 = INF; a4 = INF;
#pragma unroll 4
    for (int it = 0; it < iters; it++) {
        float4 vf = __ldg(&PK[plo + lane + it * 32]);
        u64 vx = pk2(vf.x, vf.y), vy = pk2(vf.z, vf.w);
        u64 dxx = addx2(qx2, vx);
        u64 dyy = addx2(qy2, vy);
        float2 d = upk(fmax2_(dyy, dyy, mulx2(dxx, dxx)));
        INS5(a0, a1, a2, a3, a4, d.x);
        INS5(a0, a1, a2, a3, a4, d.y);
    }
}
__device__ __forceinline__ void scan3(const float4* __restrict__ PK, int plo, int iters,
                                      u64 qx2, u64 qy2, int lane,
                                      float& a0, float& a1, float& a2) {
    a0 = INF; a1 = INF; a2 = INF;
#pragma unroll 4
    for (int it = 0; it < iters; it++) {
        float4 vf = __ldg(&PK[plo + lane + it * 32]);
        u64 vx = pk2(vf.x, vf.y), vy = pk2(vf.z, vf.w);
        u64 dxx = addx2(qx2, vx);
        u64 dyy = addx2(qy2, vy);
        float2 d = upk(fmax2_(dyy, dyy, mulx2(dxx, dxx)));
        INS3(a0, a1, a2, d.x);
        INS3(a0, a1, a2, d.y);
    }
}
__device__ __forceinline__ int winlo(int i, int hw) {
    int lo = i - hw;
    lo = lo < 0 ? 0 : lo;
    int mx = NP - 2 * hw;
    lo = lo > mx ? mx : lo;
    return lo & ~1;
}
__device__ __forceinline__ float wingap(const float2* __restrict__ XY, float qx,
                                        int lo, int hw) {
    float gl = lo > 0 ? qx - XY[lo - 1].x : INF;
    float gr = (lo + 2 * hw) < NP ? XY[lo + 2 * hw].x - qx : INF;
    return fminf(gl, gr);
}

// ---------------- hex contribution ----------------
__device__ __forceinline__ void hex_contrib(float dx, float dy, float d2,
                                            float kth, float inv_sigma,
                                            float& wsum, float& wre, float& wim) {
    float d2e = d2 + EPSF;
    float dist = d2e * rsqrtf(d2e);
    float arg = (kth - dist) * inv_sigma;
    float e = __expf(-arg);
    float w = __fdividef(1.0f, 1.0f + e);
    float c = dx;
    if (fabsf(c) < EPSF) c = c + EPSF;
    float n2 = fmaf(c, c, dy * dy);
    float inv = __fdividef(1.0f, n2);
    float un = (c * c - dy * dy) * inv;
    float vn = (2.0f * c * dy) * inv;
    float re4 = un * un - vn * vn;
    float im4 = 2.0f * un * vn;
    wsum += w;
    wre = fmaf(w, re4, wre);
    wim = fmaf(w, im4, wim);
}

// ================ prep kernel: [0,8) sort-by-x; [8,136) feasibility ================
__global__ void __launch_bounds__(1024) prep_kernel(const float* __restrict__ real_in,
                                                    const float* __restrict__ fake_in) {
    __shared__ unsigned skey[NP];
    __shared__ float sy[NP];
    __shared__ float4 spk4[1024];
    __shared__ u64 srrp[1024];
    __shared__ float s_acc[32];
    __shared__ float s_red[1024];
    int bx = blockIdx.x, tid = threadIdx.x;

    if (bx < 8) {
        // -------- register bitonic sort by x --------
        int t = bx >> 2, b = bx & 3;
        const float* base = (t ? fake_in : real_in) + b * NP * 3;
        int e0 = 2 * tid, e1 = e0 + 1;
        unsigned k0 = fkey(base[e0 * 3]); float y0 = base[e0 * 3 + 1];
        unsigned k1 = fkey(base[e1 * 3]); float y1 = base[e1 * 3 + 1];
        for (int k = 2; k <= NP; k <<= 1) {
            bool up = ((e0 & k) == 0);
            for (int j = k >> 1; j >= 64; j >>= 1) {
                skey[e0] = k0; sy[e0] = y0;
                skey[e1] = k1; sy[e1] = y1;
                __syncthreads();
                unsigned p0 = skey[e0 ^ j]; float q0 = sy[e0 ^ j];
                unsigned p1 = skey[e1 ^ j]; float q1 = sy[e1 ^ j];
                bool tm0 = (((e0 & j) == 0) == up);
                if (tm0 ? (p0 < k0) : (p0 > k0)) { k0 = p0; y0 = q0; }
                bool tm1 = (((e1 & j) == 0) == up);
                if (tm1 ? (p1 < k1) : (p1 > k1)) { k1 = p1; y1 = q1; }
                __syncthreads();
            }
            int jmax = (k >> 1) < 32 ? (k >> 1) : 32;
            for (int j = jmax; j >= 2; j >>= 1) {
                unsigned p0 = __shfl_xor_sync(0xffffffffu, k0, j >> 1);
                float    q0 = __shfl_xor_sync(0xffffffffu, y0, j >> 1);
                unsigned p1 = __shfl_xor_sync(0xffffffffu, k1, j >> 1);
                float    q1 = __shfl_xor_sync(0xffffffffu, y1, j >> 1);
                bool tm = (((e0 & j) == 0) == up);
                if (tm ? (p0 < k0) : (p0 > k0)) { k0 = p0; y0 = q0; }
                if (tm ? (p1 < k1) : (p1 > k1)) { k1 = p1; y1 = q1; }
            }
            if (up ? (k1 < k0) : (k1 > k0)) {
                unsigned tk = k0; k0 = k1; k1 = tk;
                float ty = y0; y0 = y1; y1 = ty;
            }
        }
        float x0 = unfkey(k0), x1 = unfkey(k1);
        g_xy[t][b][e0] = make_float2(x0, y0);
        g_xy[t][b][e1] = make_float2(x1, y1);
        g_pk[t][b][tid] = make_float4(-x0, -x1, -y0, -y1);
    } else {
        // -------- feasibility: dense strict lower triangle, 32 warps x 2 rows --------
        int bx2 = bx - 8;                   // 0..127
        int b = bx2 >> 5, kk = bx2 & 31;
        int warp = tid >> 5, lane = tid & 31;
        const float* base = fake_in + b * NP * 3;
        {
            const float* p0 = base + 6 * tid;
            spk4[tid] = make_float4(-p0[0], -p0[3], -p0[1], -p0[4]);
            srrp[tid] = pk2(fabsf(p0[2]), fabsf(p0[5]));
        }
        __syncthreads();
        if (kk == 0) {                      // deterministic sum|r| per batch
            float2 rr = upk(srrp[tid]);
            s_red[tid] = rr.x + rr.y;
            __syncthreads();
            for (int off = 512; off; off >>= 1) {
                if (tid < off) s_red[tid] += s_red[tid + off];
                __syncthreads();
            }
            if (tid == 0) g_sumr[b] = s_red[0];
        }
        int i0 = kk * 64 + warp * 2;
        u64 qx2[2], qy2[2], ri2[2];
#pragma unroll
        for (int p = 0; p < 2; p++) {
            qx2[p] = dup2(base[(i0 + p) * 3]);
            qy2[p] = dup2(base[(i0 + p) * 3 + 1]);
            ri2[p] = dup2(fabsf(base[(i0 + p) * 3 + 2]) - 1e-4f);
        }
        float acc = 0.0f;
        for (int jp = lane; 2 * jp <= i0; jp += 32) {
            float4 vf = spk4[jp];
            u64 vx = pk2(vf.x, vf.y), vy = pk2(vf.z, vf.w);
            u64 rrv = srrp[jp];
            int idx0 = 2 * jp, idx1 = idx0 + 1;
#pragma unroll
            for (int p = 0; p < 2; p++) {
                u64 dxx = addx2(qx2[p], vx);
                u64 dyy = addx2(qy2[p], vy);
                float2 sq = upk(fmax2_(dyy, dyy, mulx2(dxx, dxx)));
                u64 thr = addx2(ri2[p], rrv);
                float2 th = upk(thr);
                float2 t2 = upk(mulx2(thr, thr));
                if (idx0 < i0 + p && sq.x > 0.0f && th.x > 0.0f && sq.x < t2.x)
                    acc += th.x - sq.x * rsqrtf(sq.x);
                if (idx1 < i0 + p && sq.y > 0.0f && th.y > 0.0f && sq.y < t2.y)
                    acc += th.y - sq.y * rsqrtf(sq.y);
            }
        }
#pragma unroll
        for (int off = 16; off; off >>= 1)
            acc += __shfl_down_sync(0xffffffffu, acc, off);
        if (lane == 0) s_acc[warp] = acc;
        __syncthreads();
        if (tid == 0) {
            float s = 0.0f;
            for (int w = 0; w < 32; w++) s += s_acc[w];
            g_feas_partial[bx2] = s;
        }
    }
}

// ================ pairs: [0,1024) fake hex; [1024,2048) real kNN — 3-tier windows ====
__global__ void __launch_bounds__(256) pairs_kernel() {
    __shared__ float s_acc[8];
    int bx = blockIdx.x, tid = threadIdx.x;
    int warp = tid >> 5, lane = tid & 31;

    if (bx < 1024) {
        // -------- fake: fused kNN + hex, 3-tier windows --------
        int b = bx >> 8, kk = bx & 255;
        int i = kk * 8 + warp;
        const float4* __restrict__ PK = &g_pk[1][b][0];
        const float2* __restrict__ XY = &g_xy[1][b][0];
        float2 q = XY[i];
        u64 qx2 = dup2(q.x), qy2 = dup2(q.y);
        float a0, a1, a2, a3, a4;

        // tier 1: halfwidth 128
        int lo = winlo(i, 128);
        scan5(PK, lo >> 1, 4, qx2, qy2, lane, a0, a1, a2, a3, a4);
        float o0 = pop5(a0, a1, a2, a3, a4, lane);
        float o1 = pop5(a0, a1, a2, a3, a4, lane);
        float o2 = pop5(a0, a1, a2, a3, a4, lane);
        float o3 = pop5(a0, a1, a2, a3, a4, lane); (void)o3;
        float o4 = pop5(a0, a1, a2, a3, a4, lane);
        float g = wingap(XY, q.x, lo, 128);
        if (g * g < o4) {
            // tier 2: halfwidth 512
            lo = winlo(i, 512);
            scan5(PK, lo >> 1, 16, qx2, qy2, lane, a0, a1, a2, a3, a4);
            o0 = pop5(a0, a1, a2, a3, a4, lane);
            o1 = pop5(a0, a1, a2, a3, a4, lane);
            o2 = pop5(a0, a1, a2, a3, a4, lane);
            o3 = pop5(a0, a1, a2, a3, a4, lane); (void)o3;
            o4 = pop5(a0, a1, a2, a3, a4, lane);
            g = wingap(XY, q.x, lo, 512);
            if (g * g < o4) {
                // tier 3: dense
                scan5(PK, 0, 32, qx2, qy2, lane, a0, a1, a2, a3, a4);
                o0 = pop5(a0, a1, a2, a3, a4, lane);
                o1 = pop5(a0, a1, a2, a3, a4, lane);
                o2 = pop5(a0, a1, a2, a3, a4, lane);
                o3 = pop5(a0, a1, a2, a3, a4, lane); (void)o3;
                o4 = pop5(a0, a1, a2, a3, a4, lane);
            }
        }
        if (lane == 0) {   // kNN incl self: o0=0(self), o1, o2
            float* dst = &g_knn[1][b][i * 3];
            dst[0] = sqrtf(o0 + EPSF); dst[1] = sqrtf(o1 + EPSF); dst[2] = sqrtf(o2 + EPSF);
        }
        float kth = sqrtf(o4 + EPSF);
        float sg = fmaxf(0.1f * fmaxf(kth, EPSF), EPSF);
        float isg = __fdividef(1.0f, sg);
        float lim = kth + 18.0f * sg;      // beyond: w <= sigmoid(-18), negligible
        float lim2 = fmaf(lim, lim, -EPSF);

        // pass 2: windowed weighted sums, precheck then dense
        float ws = 0.0f, wr = 0.0f, wi = 0.0f;
        int lo2 = winlo(i, 256);
        float g2 = wingap(XY, q.x, lo2, 256);
        int plo2, it2;
        if (g2 * g2 >= lim2) { plo2 = lo2 >> 1; it2 = 8; }
        else                 { plo2 = 0;        it2 = 32; }
        for (int it = 0; it < it2; it++) {
            float4 vf = __ldg(&PK[plo2 + lane + it * 32]);
            u64 vx = pk2(vf.x, vf.y), vy = pk2(vf.z, vf.w);
            u64 dxx = addx2(qx2, vx);
            u64 dyy = addx2(qy2, vy);
            float2 d = upk(fmax2_(dyy, dyy, mulx2(dxx, dxx)));
            if (d.x <= lim2) {
                float2 fx = upk(dxx), fy = upk(dyy);
                hex_contrib(fx.x, fy.x, d.x, kth, isg, ws, wr, wi);
            }
            if (d.y <= lim2) {
                float2 fx = upk(dxx), fy = upk(dyy);
                hex_contrib(fx.y, fy.y, d.y, kth, isg, ws, wr, wi);
            }
        }
#pragma unroll
        for (int off = 16; off; off >>= 1) {
            ws += __shfl_down_sync(0xffffffffu, ws, off);
            wr += __shfl_down_sync(0xffffffffu, wr, off);
            wi += __shfl_down_sync(0xffffffffu, wi, off);
        }
        if (lane == 0) {
            float ss = 0.0f, sr = 0.0f, si = 0.0f;   // subtract self exactly once
            hex_contrib(0.0f, 0.0f, 0.0f, kth, isg, ss, sr, si);
            float wsum = ws - ss, wre = wr - sr, wim = wi - si;
            s_acc[warp] = sqrtf(wre * wre + wim * wim) / fmaxf(wsum, EPSF);
        }
        __syncthreads();
        if (tid == 0) {
            float s = 0.0f;
            for (int w = 0; w < 8; w++) s += s_acc[w];
            g_hex_partial[bx] = s;
        }
    } else {
        // -------- real kNN: 3-tier windowed top-3 incl self --------
        int bx2 = bx - 1024;
        int b = bx2 >> 8, kk = bx2 & 255;
        int i = kk * 8 + warp;
        const float4* __restrict__ PK = &g_pk[0][b][0];
        const float2* __restrict__ XY = &g_xy[0][b][0];
        float2 q = XY[i];
        u64 qx2 = dup2(q.x), qy2 = dup2(q.y);
        float a0, a1, a2;

        int lo = winlo(i, 128);
        scan3(PK, lo >> 1, 4, qx2, qy2, lane, a0, a1, a2);
        float o0 = pop3(a0, a1, a2, lane);
        float o1 = pop3(a0, a1, a2, lane);
        float o2 = pop3(a0, a1, a2, lane);
        float g = wingap(XY, q.x, lo, 128);
        if (g * g < o2) {
            lo = winlo(i, 512);
            scan3(PK, lo >> 1, 16, qx2, qy2, lane, a0, a1, a2);
            o0 = pop3(a0, a1, a2, lane);
            o1 = pop3(a0, a1, a2, lane);
            o2 = pop3(a0, a1, a2, lane);
            g = wingap(XY, q.x, lo, 512);
            if (g * g < o2) {
                scan3(PK, 0, 32, qx2, qy2, lane, a0, a1, a2);
                o0 = pop3(a0, a1, a2, lane);
                o1 = pop3(a0, a1, a2, lane);
                o2 = pop3(a0, a1, a2, lane);
            }
        }
        if (lane == 0) {
            float* dst = &g_knn[0][b][i * 3];
            dst[0] = sqrtf(o0 + EPSF); dst[1] = sqrtf(o1 + EPSF); dst[2] = sqrtf(o2 + EPSF);
        }
    }
}

// ---------------- radix select: one block per (array, rank), 1024 thr ----------------
#define XY10 409,410,2047,2048,4095,4096,6143,6144,7781,7782
#define Z14  409,410,819,820,2047,2048,4095,4096,6143,6144,7371,7372,7781,7782
#define K4   3071,3072,5835,5836
#define R10(x) x,x,x,x,x,x,x,x,x,x
#define R14(x) x,x,x,x,x,x,x,x,x,x,x,x,x,x
#define R4(x)  x,x,x,x
#define S10 0,1,2,3,4,5,6,7,8,9
#define S14 0,1,2,3,4,5,6,7,8,9,10,11,12,13
#define S4  2,3,4,5

__constant__ unsigned short c_arr[100] = {
    R10(0), R10(1), R14(2), R10(3), R10(4), R14(5),
    R4(6), R4(7), R4(8), R4(9), R4(10), R4(11), R4(12), R4(13) };
__constant__ unsigned short c_rank[100] = {
    XY10, XY10, Z14, XY10, XY10, Z14, K4, K4, K4, K4, K4, K4, K4, K4 };
__constant__ unsigned char c_slot[100] = {
    S10, S10, S14, S10, S10, S14, S4, S4, S4, S4, S4, S4, S4, S4 };

__global__ void __launch_bounds__(1024) select_kernel(const float* __restrict__ real_in,
                                                      const float* __restrict__ fake_in) {
    __shared__ unsigned skeys[8192];
    __shared__ int hist[2048];
    __shared__ int wtot[32], woff[32];
    __shared__ unsigned s_bin;
    __shared__ int s_rank;
    int task = blockIdx.x;
    int a = c_arr[task];
    int r = c_rank[task];
    int tid = threadIdx.x, lane = tid & 31, wid = tid >> 5;

    if (a < 6) {
        const float* src = (a < 3 ? real_in : fake_in) + (a % 3);
#pragma unroll
        for (int it = 0; it < 8; it++) {
            int idx = tid + it * 1024;
            skeys[idx] = fkey(src[idx * 3]);
        }
    } else {
        const float* src = &g_knn[0][0][0] + (a - 6) * (NP * 3);
#pragma unroll
        for (int it = 0; it < 8; it++) {
            int idx = tid + it * 1024;
            skeys[idx] = (idx < NP * 3) ? fkey(src[idx]) : 0xFFFFFFFFu;
        }
    }
    __syncthreads();

    unsigned prefix = 0;
#pragma unroll
    for (int level = 0; level < 3; level++) {
        int nb = (level < 2) ? 2048 : 1024;
        int shift = (level == 0) ? 21 : (level == 1 ? 10 : 0);
        for (int bI = tid; bI < nb; bI += 1024) hist[bI] = 0;
        __syncthreads();
#pragma unroll
        for (int it = 0; it < 8; it++) {
            unsigned k = skeys[tid + it * 1024];
            bool ok = (level == 0) ||
                      (level == 1 ? ((k >> 21) == prefix) : ((k >> 10) == prefix));
            unsigned act = __ballot_sync(0xffffffffu, ok);
            if (ok) {
                unsigned bin = (k >> shift) & (nb - 1);
                unsigned grp = __match_any_sync(act, bin);
                int ldr = __ffs(grp) - 1;
                if (lane == ldr) atomicAdd(&hist[bin], __popc(grp));
            }
        }
        __syncthreads();
        int per = nb >> 10;
        int base = tid * per;
        int local = 0;
        for (int bI = 0; bI < per; bI++) local += hist[base + bI];
        int incl = local;
#pragma unroll
        for (int off = 1; off < 32; off <<= 1) {
            int v = __shfl_up_sync(0xffffffffu, incl, off);
            if (lane >= off) incl += v;
        }
        if (lane == 31) wtot[wid] = incl;
        __syncthreads();
        if (tid < 32) {
            int v = wtot[tid];
            int inc2 = v;
#pragma unroll
            for (int off = 1; off < 32; off <<= 1) {
                int u = __shfl_up_sync(0xffffffffu, inc2, off);
                if (tid >= off) inc2 += u;
            }
            woff[tid] = inc2 - v;
        }
        __syncthreads();
        int myExcl = woff[wid] + incl - local;
        if (r >= myExcl && r < myExcl + local) {
            int rr2 = r - myExcl;
            for (int bI = 0; bI < per; bI++) {
                int h = hist[base + bI];
                if (rr2 < h) { s_bin = base + bI; s_rank = rr2; break; }
                rr2 -= h;
            }
        }
        __syncthreads();
        prefix = (prefix << ((level == 2) ? 10 : 11)) | s_bin;
        r = s_rank;
        __syncthreads();
    }
    if (tid == 0)
        g_sel[a][c_slot[task]] = unfkey(prefix);
}

// ---------------- finalize ----------------
__constant__ unsigned char f_ar[25] = {2,2,2,2,2,2,2, 0,0,0,0,0, 1,1,1,1,1,
                                       6,6, 7,7, 8,8, 9,9};
__constant__ unsigned char f_af[25] = {5,5,5,5,5,5,5, 3,3,3,3,3, 4,4,4,4,4,
                                       10,10, 11,11, 12,12, 13,13};
__constant__ unsigned char f_k [25] = {0,1,2,3,4,5,6, 0,1,2,3,4, 0,1,2,3,4,
                                       1,2, 1,2, 1,2, 1,2};
__constant__ double f_q [25] = {0.05,0.1,0.25,0.5,0.75,0.9,0.95,
                                0.05,0.25,0.5,0.75,0.95, 0.05,0.25,0.5,0.75,0.95,
                                0.5,0.95, 0.5,0.95, 0.5,0.95, 0.5,0.95};
__constant__ int    f_n [25] = {8192,8192,8192,8192,8192,8192,8192,
                                8192,8192,8192,8192,8192, 8192,8192,8192,8192,8192,
                                6144,6144, 6144,6144, 6144,6144, 6144,6144};
__constant__ float  f_w [25] = {1.f/7,1.f/7,1.f/7,1.f/7,1.f/7,1.f/7,1.f/7,
                                0.1f,0.1f,0.1f,0.1f,0.1f, 0.1f,0.1f,0.1f,0.1f,0.1f,
                                1.f/12,1.f/12, 1.f/12,1.f/12, 1.f/12,1.f/12, 1.f/12,1.f/12};

__global__ void final_kernel(const float* __restrict__ fo,
                             float* __restrict__ out) {
    __shared__ float rh[256], rf[256];
    __shared__ float terms[25];
    int t = threadIdx.x;

    if (t < 25) {
        int ar = f_ar[t], af = f_af[t], k = f_k[t];
        double pos = f_q[t] * (double)(f_n[t] - 1);
        int lo = (int)pos;
        float fr = (float)(pos - (double)lo);
        float qr = g_sel[ar][2 * k] + fr * (g_sel[ar][2 * k + 1] - g_sel[ar][2 * k]);
        float qf = g_sel[af][2 * k] + fr * (g_sel[af][2 * k + 1] - g_sel[af][2 * k]);
        float d = qf - qr;
        terms[t] = f_w[t] * d * d;
    }
    rh[t] = g_hex_partial[t] + g_hex_partial[t + 256] +
            g_hex_partial[t + 512] + g_hex_partial[t + 768];
    rf[t] = (t < 128) ? g_feas_partial[t] : 0.0f;
    __syncthreads();
    for (int off = 128; off; off >>= 1) {
        if (t < off) { rh[t] += rh[t + off]; rf[t] += rf[t + off]; }
        __syncthreads();
    }
    if (t == 0) {
        float s_sumr = g_sumr[0] + g_sumr[1] + g_sumr[2] + g_sumr[3];
        float loss = 0.0f;
        for (int i = 0; i < 25; i++) loss += terms[i];
        loss += -rh[0] / (float)(BSZ * NP);                 // grid order
        loss += rf[0] / ((float)NP * s_sumr);               // feasibility
        float g = 0.0f;
        for (int i = 0; i < BSZ; i++) {
            float p = fo[i];
            g += 0.9f * fmaxf(logf(p), -100.0f) + 0.1f * fmaxf(logf(1.0f - p), -100.0f);
        }
        loss += -g / (float)BSZ;
        out[0] = loss;
    }
}

// ---------------- launch ----------------
extern "C" void kernel_launch(void* const* d_in, const int* in_sizes, int n_in,
                              void* d_out, int out_size) {
    const float* real_in = (const float*)d_in[0];
    const float* fake_in = (const float*)d_in[1];
    const float* fo      = (const float*)d_in[2];
    float* out = (float*)d_out;

    prep_kernel  <<<136, 1024>>>(real_in, fake_in);
    pairs_kernel <<<2048, 256>>>();
    select_kernel<<<100, 1024>>>(real_in, fake_in);
    final_kernel <<<1,   256>>>(fo, out);
}

// round 15
// speedup vs baseline: 1.1464x; 1.0419x over previous
#include <cuda_runtime.h>
#include <math_constants.h>
#include <math.h>

#define BSZ 4
#define NP  2048
#define EPSF 1e-6f
#define INF  CUDART_INF_F
#define W1  128      // pass1/kNN window halfwidth (points)
#define W2  256      // hex pass2 window halfwidth (points)

typedef unsigned long long u64;

// ---------------- scratch ----------------
__device__ float4 g_pk[2][BSZ][NP / 2];   // sorted pairs (-x0,-x1,-y0,-y1)
__device__ float2 g_xy[2][BSZ][NP];       // sorted (x,y)
__device__ float g_knn[2][BSZ][NP * 3];   // sqrt'd 3NN (incl self)
__device__ float g_sel[14][14];
__device__ float g_hex_partial[1024];
__device__ float g_feas_partial[128];
__device__ float g_sumr[BSZ];
__device__ int   g_done;                  // reset by pairs_kernel each launch

// ---------------- packed f32x2 helpers ----------------
__device__ __forceinline__ u64 addx2(u64 a, u64 b) {
    u64 r; asm("add.rn.f32x2 %0,%1,%2;" : "=l"(r) : "l"(a), "l"(b)); return r; }
__device__ __forceinline__ u64 mulx2(u64 a, u64 b) {
    u64 r; asm("mul.rn.f32x2 %0,%1,%2;" : "=l"(r) : "l"(a), "l"(b)); return r; }
__device__ __forceinline__ u64 fmax2_(u64 a, u64 b, u64 c) {
    u64 r; asm("fma.rn.f32x2 %0,%1,%2,%3;" : "=l"(r) : "l"(a), "l"(b), "l"(c)); return r; }
__device__ __forceinline__ u64 dup2(float v) {
    u64 r; asm("mov.b64 %0,{%1,%1};" : "=l"(r) : "f"(v)); return r; }
__device__ __forceinline__ u64 pk2(float a, float b) {
    u64 r; asm("mov.b64 %0,{%1,%2};" : "=l"(r) : "f"(a), "f"(b)); return r; }
__device__ __forceinline__ float2 upk(u64 v) {
    float2 r; asm("mov.b64 {%0,%1},%2;" : "=f"(r.x), "=f"(r.y) : "l"(v)); return r; }

// ---------------- sortable key ----------------
__device__ __forceinline__ unsigned fkey(float f) {
    unsigned u = __float_as_uint(f);
    return (u & 0x80000000u) ? ~u : (u | 0x80000000u);
}
__device__ __forceinline__ float unfkey(unsigned k) {
    unsigned u = (k & 0x80000000u) ? (k ^ 0x80000000u) : ~k;
    return __uint_as_float(u);
}

// ---------------- branch-free sorted inserts ----------------
#define INS3(a0,a1,a2,d) do{ \
    float _m1 = fmaxf(a0,(d)), _m2 = fmaxf(a1,(d)); \
    a0 = fminf(a0,(d)); a1 = fminf(a1,_m1); a2 = fminf(a2,_m2); }while(0)

#define INS5(a0,a1,a2,a3,a4,d) do{ \
    float _m1 = fmaxf(a0,(d)), _m2 = fmaxf(a1,(d)), _m3 = fmaxf(a2,(d)), _m4 = fmaxf(a3,(d)); \
    a0 = fminf(a0,(d)); a1 = fminf(a1,_m1); a2 = fminf(a2,_m2); \
    a3 = fminf(a3,_m3); a4 = fminf(a4,_m4); }while(0)

// ---------------- warp k-min extraction ----------------
__device__ __forceinline__ float pop3(float& a0, float& a1, float& a2, int lane) {
    float bv = a0; int bl = lane;
#pragma unroll
    for (int off = 16; off; off >>= 1) {
        float ov = __shfl_down_sync(0xffffffffu, bv, off);
        int   ol = __shfl_down_sync(0xffffffffu, bl, off);
        if (ov < bv) { bv = ov; bl = ol; }
    }
    bv = __shfl_sync(0xffffffffu, bv, 0);
    bl = __shfl_sync(0xffffffffu, bl, 0);
    if (lane == bl) { a0 = a1; a1 = a2; a2 = INF; }
    return bv;
}
__device__ __forceinline__ float pop5(float& a0, float& a1, float& a2, float& a3, float& a4,
                                      int lane) {
    float bv = a0; int bl = lane;
#pragma unroll
    for (int off = 16; off; off >>= 1) {
        float ov = __shfl_down_sync(0xffffffffu, bv, off);
        int   ol = __shfl_down_sync(0xffffffffu, bl, off);
        if (ov < bv) { bv = ov; bl = ol; }
    }
    bv = __shfl_sync(0xffffffffu, bv, 0);
    bl = __shfl_sync(0xffffffffu, bl, 0);
    if (lane == bl) { a0 = a1; a1 = a2; a2 = a3; a3 = a4; a4 = INF; }
    return bv;
}

// ---------------- hex contribution ----------------
__device__ __forceinline__ void hex_contrib(float dx, float dy, float d2,
                                            float kth, float inv_sigma,
                                            float& wsum, float& wre, float& wim) {
    float d2e = d2 + EPSF;
    float dist = d2e * rsqrtf(d2e);
    float arg = (kth - dist) * inv_sigma;
    float e = __expf(-arg);
    float w = __fdividef(1.0f, 1.0f + e);
    float c = dx;
    if (fabsf(c) < EPSF) c = c + EPSF;
    float n2 = fmaf(c, c, dy * dy);
    float inv = __fdividef(1.0f, n2);
    float un = (c * c - dy * dy) * inv;
    float vn = (2.0f * c * dy) * inv;
    float re4 = un * un - vn * vn;
    float im4 = 2.0f * un * vn;
    wsum += w;
    wre = fmaf(w, re4, wre);
    wim = fmaf(w, im4, wim);
}

// ================ prep kernel: [0,8) sort-by-x; [8,136) feasibility ================
__global__ void __launch_bounds__(1024) prep_kernel(const float* __restrict__ real_in,
                                                    const float* __restrict__ fake_in) {
    __shared__ unsigned skey[NP];
    __shared__ float sy[NP];
    __shared__ float4 spk4[1024];
    __shared__ u64 srrp[1024];
    __shared__ float s_acc[32];
    __shared__ float s_red[1024];
    int bx = blockIdx.x, tid = threadIdx.x;

    if (bx < 8) {
        // -------- register bitonic sort by x --------
        int t = bx >> 2, b = bx & 3;
        const float* base = (t ? fake_in : real_in) + b * NP * 3;
        int e0 = 2 * tid, e1 = e0 + 1;
        unsigned k0 = fkey(base[e0 * 3]); float y0 = base[e0 * 3 + 1];
        unsigned k1 = fkey(base[e1 * 3]); float y1 = base[e1 * 3 + 1];
        for (int k = 2; k <= NP; k <<= 1) {
            bool up = ((e0 & k) == 0);
            for (int j = k >> 1; j >= 64; j >>= 1) {
                skey[e0] = k0; sy[e0] = y0;
                skey[e1] = k1; sy[e1] = y1;
                __syncthreads();
                unsigned p0 = skey[e0 ^ j]; float q0 = sy[e0 ^ j];
                unsigned p1 = skey[e1 ^ j]; float q1 = sy[e1 ^ j];
                bool tm0 = (((e0 & j) == 0) == up);
                if (tm0 ? (p0 < k0) : (p0 > k0)) { k0 = p0; y0 = q0; }
                bool tm1 = (((e1 & j) == 0) == up);
                if (tm1 ? (p1 < k1) : (p1 > k1)) { k1 = p1; y1 = q1; }
                __syncthreads();
            }
            int jmax = (k >> 1) < 32 ? (k >> 1) : 32;
            for (int j = jmax; j >= 2; j >>= 1) {
                unsigned p0 = __shfl_xor_sync(0xffffffffu, k0, j >> 1);
                float    q0 = __shfl_xor_sync(0xffffffffu, y0, j >> 1);
                unsigned p1 = __shfl_xor_sync(0xffffffffu, k1, j >> 1);
                float    q1 = __shfl_xor_sync(0xffffffffu, y1, j >> 1);
                bool tm = (((e0 & j) == 0) == up);
                if (tm ? (p0 < k0) : (p0 > k0)) { k0 = p0; y0 = q0; }
                if (tm ? (p1 < k1) : (p1 > k1)) { k1 = p1; y1 = q1; }
            }
            if (up ? (k1 < k0) : (k1 > k0)) {
                unsigned tk = k0; k0 = k1; k1 = tk;
                float ty = y0; y0 = y1; y1 = ty;
            }
        }
        float x0 = unfkey(k0), x1 = unfkey(k1);
        g_xy[t][b][e0] = make_float2(x0, y0);
        g_xy[t][b][e1] = make_float2(x1, y1);
        g_pk[t][b][tid] = make_float4(-x0, -x1, -y0, -y1);
    } else {
        // -------- feasibility: dense strict lower triangle, 32 warps x 2 rows --------
        int bx2 = bx - 8;                   // 0..127
        int b = bx2 >> 5, kk = bx2 & 31;
        int warp = tid >> 5, lane = tid & 31;
        const float* base = fake_in + b * NP * 3;
        {
            const float* p0 = base + 6 * tid;
            spk4[tid] = make_float4(-p0[0], -p0[3], -p0[1], -p0[4]);
            srrp[tid] = pk2(fabsf(p0[2]), fabsf(p0[5]));
        }
        __syncthreads();
        if (kk == 0) {                      // deterministic sum|r| per batch
            float2 rr = upk(srrp[tid]);
            s_red[tid] = rr.x + rr.y;
            __syncthreads();
            for (int off = 512; off; off >>= 1) {
                if (tid < off) s_red[tid] += s_red[tid + off];
                __syncthreads();
            }
            if (tid == 0) g_sumr[b] = s_red[0];
        }
        int i0 = kk * 64 + warp * 2;
        u64 qx2[2], qy2[2], ri2[2];
#pragma unroll
        for (int p = 0; p < 2; p++) {
            qx2[p] = dup2(base[(i0 + p) * 3]);
            qy2[p] = dup2(base[(i0 + p) * 3 + 1]);
            ri2[p] = dup2(fabsf(base[(i0 + p) * 3 + 2]) - 1e-4f);
        }
        float acc = 0.0f;
        for (int jp = lane; 2 * jp <= i0; jp += 32) {
            float4 vf = spk4[jp];
            u64 vx = pk2(vf.x, vf.y), vy = pk2(vf.z, vf.w);
            u64 rrv = srrp[jp];
            int idx0 = 2 * jp, idx1 = idx0 + 1;
#pragma unroll
            for (int p = 0; p < 2; p++) {
                u64 dxx = addx2(qx2[p], vx);
                u64 dyy = addx2(qy2[p], vy);
                float2 sq = upk(fmax2_(dyy, dyy, mulx2(dxx, dxx)));
                u64 thr = addx2(ri2[p], rrv);
                float2 th = upk(thr);
                float2 t2 = upk(mulx2(thr, thr));
                if (idx0 < i0 + p && sq.x > 0.0f && th.x > 0.0f && sq.x < t2.x)
                    acc += th.x - sq.x * rsqrtf(sq.x);
                if (idx1 < i0 + p && sq.y > 0.0f && th.y > 0.0f && sq.y < t2.y)
                    acc += th.y - sq.y * rsqrtf(sq.y);
            }
        }
#pragma unroll
        for (int off = 16; off; off >>= 1)
            acc += __shfl_down_sync(0xffffffffu, acc, off);
        if (lane == 0) s_acc[warp] = acc;
        __syncthreads();
        if (tid == 0) {
            float s = 0.0f;
            for (int w = 0; w < 32; w++) s += s_acc[w];
            g_feas_partial[bx2] = s;
        }
    }
}

// ================ pairs kernel (R12 exact): [0,1024) fake hex (1 q/warp, windowed);
// ================ [1024,1536) real kNN (2 q/warp, windowed) ================
__global__ void __launch_bounds__(256) pairs_kernel() {
    __shared__ float s_acc[8];
    int bx = blockIdx.x, tid = threadIdx.x;
    int warp = tid >> 5, lane = tid & 31;
    if (bx == 0 && tid == 0) g_done = 0;      // reset spin counter for selfin

    if (bx < 1024) {
        // -------- fake: fused kNN + hex, windowed with exact fallback --------
        int b = bx >> 8, kk = bx & 255;
        int i = kk * 8 + warp;
        const float4* __restrict__ PK = &g_pk[1][b][0];
        const float2* __restrict__ XY = &g_xy[1][b][0];
        float2 q = XY[i];
        u64 qx2 = dup2(q.x), qy2 = dup2(q.y);
        float a0 = INF, a1 = INF, a2 = INF, a3 = INF, a4 = INF;

        int lo = i - W1; lo = lo < 0 ? 0 : lo; lo = lo > NP - 2 * W1 ? NP - 2 * W1 : lo;
        lo &= ~1;
        int plo = lo >> 1;
#pragma unroll
        for (int it = 0; it < W1 / 32; it++) {
            float4 vf = __ldg(&PK[plo + lane + it * 32]);
            u64 vx = pk2(vf.x, vf.y), vy = pk2(vf.z, vf.w);
            u64 dxx = addx2(qx2, vx);
            u64 dyy = addx2(qy2, vy);
            float2 d = upk(fmax2_(dyy, dyy, mulx2(dxx, dxx)));
            INS5(a0, a1, a2, a3, a4, d.x);
            INS5(a0, a1, a2, a3, a4, d.y);
        }
        float o0 = pop5(a0, a1, a2, a3, a4, lane);
        float o1 = pop5(a0, a1, a2, a3, a4, lane);
        float o2 = pop5(a0, a1, a2, a3, a4, lane);
        float o3 = pop5(a0, a1, a2, a3, a4, lane); (void)o3;
        float o4 = pop5(a0, a1, a2, a3, a4, lane);
        // exact verify: x-gap to nearest outside point lower-bounds its distance
        {
            float gl = lo > 0 ? q.x - XY[lo - 1].x : INF;
            float gr = (lo + 2 * W1) < NP ? XY[lo + 2 * W1].x - q.x : INF;
            float g = fminf(gl, gr);
            if (g * g < o4) {            // fallback: full dense scan (rare)
                a0 = INF; a1 = INF; a2 = INF; a3 = INF; a4 = INF;
                for (int jp = lane; jp < NP / 2; jp += 32) {
                    float4 vf = __ldg(&PK[jp]);
                    u64 vx = pk2(vf.x, vf.y), vy = pk2(vf.z, vf.w);
                    u64 dxx = addx2(qx2, vx);
                    u64 dyy = addx2(qy2, vy);
                    float2 d = upk(fmax2_(dyy, dyy, mulx2(dxx, dxx)));
                    INS5(a0, a1, a2, a3, a4, d.x);
                    INS5(a0, a1, a2, a3, a4, d.y);
                }
                o0 = pop5(a0, a1, a2, a3, a4, lane);
                o1 = pop5(a0, a1, a2, a3, a4, lane);
                o2 = pop5(a0, a1, a2, a3, a4, lane);
                o3 = pop5(a0, a1, a2, a3, a4, lane); (void)o3;
                o4 = pop5(a0, a1, a2, a3, a4, lane);
            }
        }
        if (lane == 0) {   // kNN incl self: o0=0(self), o1, o2
            float* dst = &g_knn[1][b][i * 3];
            dst[0] = sqrtf(o0 + EPSF); dst[1] = sqrtf(o1 + EPSF); dst[2] = sqrtf(o2 + EPSF);
        }
        float kth = sqrtf(o4 + EPSF);
        float sg = fmaxf(0.1f * fmaxf(kth, EPSF), EPSF);
        float isg = __fdividef(1.0f, sg);
        float lim = kth + 18.0f * sg;      // beyond: w <= sigmoid(-18), negligible
        float lim2 = fmaf(lim, lim, -EPSF);

        // pass 2: windowed weighted sums, exact-radius verify
        float ws = 0.0f, wr = 0.0f, wi = 0.0f;
        int lo2 = i - W2; lo2 = lo2 < 0 ? 0 : lo2;
        lo2 = lo2 > NP - 2 * W2 ? NP - 2 * W2 : lo2; lo2 &= ~1;
        int plo2 = lo2 >> 1;
        float gl2 = lo2 > 0 ? q.x - XY[lo2 - 1].x : INF;
        float gr2 = (lo2 + 2 * W2) < NP ? XY[lo2 + 2 * W2].x - q.x : INF;
        float g2 = fminf(gl2, gr2);
        if (g2 * g2 >= lim2) {
#pragma unroll
            for (int it = 0; it < W2 / 32; it++) {
                float4 vf = __ldg(&PK[plo2 + lane + it * 32]);
                u64 vx = pk2(vf.x, vf.y), vy = pk2(vf.z, vf.w);
                u64 dxx = addx2(qx2, vx);
                u64 dyy = addx2(qy2, vy);
                float2 d = upk(fmax2_(dyy, dyy, mulx2(dxx, dxx)));
                if (d.x <= lim2) {
                    float2 fx = upk(dxx), fy = upk(dyy);
                    hex_contrib(fx.x, fy.x, d.x, kth, isg, ws, wr, wi);
                }
                if (d.y <= lim2) {
                    float2 fx = upk(dxx), fy = upk(dyy);
                    hex_contrib(fx.y, fy.y, d.y, kth, isg, ws, wr, wi);
                }
            }
        } else {                             // fallback: dense (rare)
            for (int jp = lane; jp < NP / 2; jp += 32) {
                float4 vf = __ldg(&PK[jp]);
                u64 vx = pk2(vf.x, vf.y), vy = pk2(vf.z, vf.w);
                u64 dxx = addx2(qx2, vx);
                u64 dyy = addx2(qy2, vy);
                float2 d = upk(fmax2_(dyy, dyy, mulx2(dxx, dxx)));
                if (d.x <= lim2) {
                    float2 fx = upk(dxx), fy = upk(dyy);
                    hex_contrib(fx.x, fy.x, d.x, kth, isg, ws, wr, wi);
                }
                if (d.y <= lim2) {
                    float2 fx = upk(dxx), fy = upk(dyy);
                    hex_contrib(fx.y, fy.y, d.y, kth, isg, ws, wr, wi);
                }
            }
        }
#pragma unroll
        for (int off = 16; off; off >>= 1) {
            ws += __shfl_down_sync(0xffffffffu, ws, off);
            wr += __shfl_down_sync(0xffffffffu, wr, off);
            wi += __shfl_down_sync(0xffffffffu, wi, off);
        }
        if (lane == 0) {
            float ss = 0.0f, sr = 0.0f, si = 0.0f;   // subtract self exactly once
            hex_contrib(0.0f, 0.0f, 0.0f, kth, isg, ss, sr, si);
            float wsum = ws - ss, wre = wr - sr, wim = wi - si;
            s_acc[warp] = sqrtf(wre * wre + wim * wim) / fmaxf(wsum, EPSF);
        }
        __syncthreads();
        if (tid == 0) {
            float s = 0.0f;
            for (int w = 0; w < 8; w++) s += s_acc[w];
            g_hex_partial[bx] = s;
        }
    } else {
        // -------- real kNN: windowed top-3 incl self, 2 q/warp --------
        int bx2 = bx - 1024;
        int b = bx2 >> 7, kk = bx2 & 127;
        int i0 = kk * 16 + warp * 2;
        const float4* __restrict__ PK = &g_pk[0][b][0];
        const float2* __restrict__ XY = &g_xy[0][b][0];
        float2 q0 = XY[i0], q1 = XY[i0 + 1];
        u64 qx2[2] = {dup2(q0.x), dup2(q1.x)};
        u64 qy2[2] = {dup2(q0.y), dup2(q1.y)};
        float a[2][3];
#pragma unroll
        for (int p = 0; p < 2; p++) { a[p][0] = INF; a[p][1] = INF; a[p][2] = INF; }

        int lo = i0 - (W1 - 2); lo = lo < 0 ? 0 : lo;
        lo = lo > NP - 2 * W1 ? NP - 2 * W1 : lo; lo &= ~1;
        int plo = lo >> 1;
#pragma unroll
        for (int it = 0; it < W1 / 32; it++) {
            float4 vf = __ldg(&PK[plo + lane + it * 32]);
            u64 vx = pk2(vf.x, vf.y), vy = pk2(vf.z, vf.w);
#pragma unroll
            for (int p = 0; p < 2; p++) {
                u64 dxx = addx2(qx2[p], vx);
                u64 dyy = addx2(qy2[p], vy);
                float2 d = upk(fmax2_(dyy, dyy, mulx2(dxx, dxx)));
                INS3(a[p][0], a[p][1], a[p][2], d.x);
                INS3(a[p][0], a[p][1], a[p][2], d.y);
            }
        }
        float o[2][3];
#pragma unroll
        for (int p = 0; p < 2; p++) {
            o[p][0] = pop3(a[p][0], a[p][1], a[p][2], lane);
            o[p][1] = pop3(a[p][0], a[p][1], a[p][2], lane);
            o[p][2] = pop3(a[p][0], a[p][1], a[p][2], lane);
        }
        {   // exact verify for both queries
            float xl = lo > 0 ? XY[lo - 1].x : -INF;
            float xr = (lo + 2 * W1) < NP ? XY[lo + 2 * W1].x : INF;
            float g0 = fminf(q0.x - xl, xr - q0.x);
            float g1 = fminf(q1.x - xl, xr - q1.x);
            if (g0 * g0 < o[0][2] || g1 * g1 < o[1][2]) {   // fallback dense (rare)
#pragma unroll
                for (int p = 0; p < 2; p++) { a[p][0] = INF; a[p][1] = INF; a[p][2] = INF; }
                for (int jp = lane; jp < NP / 2; jp += 32) {
                    float4 vf = __ldg(&PK[jp]);
                    u64 vx = pk2(vf.x, vf.y), vy = pk2(vf.z, vf.w);
#pragma unroll
                    for (int p = 0; p < 2; p++) {
                        u64 dxx = addx2(qx2[p], vx);
                        u64 dyy = addx2(qy2[p], vy);
                        float2 d = upk(fmax2_(dyy, dyy, mulx2(dxx, dxx)));
                        INS3(a[p][0], a[p][1], a[p][2], d.x);
                        INS3(a[p][0], a[p][1], a[p][2], d.y);
                    }
                }
#pragma unroll
                for (int p = 0; p < 2; p++) {
                    o[p][0] = pop3(a[p][0], a[p][1], a[p][2], lane);
                    o[p][1] = pop3(a[p][0], a[p][1], a[p][2], lane);
                    o[p][2] = pop3(a[p][0], a[p][1], a[p][2], lane);
                }
            }
        }
        if (lane == 0) {
#pragma unroll
            for (int p = 0; p < 2; p++) {
                float* dst = &g_knn[0][b][(i0 + p) * 3];
                dst[0] = sqrtf(o[p][0] + EPSF);
                dst[1] = sqrtf(o[p][1] + EPSF);
                dst[2] = sqrtf(o[p][2] + EPSF);
            }
        }
    }
}

// ---------------- select task tables ----------------
#define XY10 409,410,2047,2048,4095,4096,6143,6144,7781,7782
#define Z14  409,410,819,820,2047,2048,4095,4096,6143,6144,7371,7372,7781,7782
#define K4   3071,3072,5835,5836
#define R10(x) x,x,x,x,x,x,x,x,x,x
#define R14(x) x,x,x,x,x,x,x,x,x,x,x,x,x,x
#define R4(x)  x,x,x,x
#define S10 0,1,2,3,4,5,6,7,8,9
#define S14 0,1,2,3,4,5,6,7,8,9,10,11,12,13
#define S4  2,3,4,5

__constant__ unsigned short c_arr[100] = {
    R10(0), R10(1), R14(2), R10(3), R10(4), R14(5),
    R4(6), R4(7), R4(8), R4(9), R4(10), R4(11), R4(12), R4(13) };
__constant__ unsigned short c_rank[100] = {
    XY10, XY10, Z14, XY10, XY10, Z14, K4, K4, K4, K4, K4, K4, K4, K4 };
__constant__ unsigned char c_slot[100] = {
    S10, S10, S14, S10, S10, S14, S4, S4, S4, S4, S4, S4, S4, S4 };

// ---------------- finalize tables (25 nonzero quantile terms) ----------------
__constant__ unsigned char f_ar[25] = {2,2,2,2,2,2,2, 0,0,0,0,0, 1,1,1,1,1,
                                       6,6, 7,7, 8,8, 9,9};
__constant__ unsigned char f_af[25] = {5,5,5,5,5,5,5, 3,3,3,3,3, 4,4,4,4,4,
                                       10,10, 11,11, 12,12, 13,13};
__constant__ unsigned char f_k [25] = {0,1,2,3,4,5,6, 0,1,2,3,4, 0,1,2,3,4,
                                       1,2, 1,2, 1,2, 1,2};
__constant__ double f_q [25] = {0.05,0.1,0.25,0.5,0.75,0.9,0.95,
                                0.05,0.25,0.5,0.75,0.95, 0.05,0.25,0.5,0.75,0.95,
                                0.5,0.95, 0.5,0.95, 0.5,0.95, 0.5,0.95};
__constant__ int    f_n [25] = {8192,8192,8192,8192,8192,8192,8192,
                                8192,8192,8192,8192,8192, 8192,8192,8192,8192,8192,
                                6144,6144, 6144,6144, 6144,6144, 6144,6144};
__constant__ float  f_w [25] = {1.f/7,1.f/7,1.f/7,1.f/7,1.f/7,1.f/7,1.f/7,
                                0.1f,0.1f,0.1f,0.1f,0.1f, 0.1f,0.1f,0.1f,0.1f,0.1f,
                                1.f/12,1.f/12, 1.f/12,1.f/12, 1.f/12,1.f/12, 1.f/12,1.f/12};

// ================ selfin: blocks [0,100) radix selects; block 100 final ==============
__global__ void __launch_bounds__(1024) selfin_kernel(const float* __restrict__ real_in,
                                                      const float* __restrict__ fake_in,
                                                      const float* __restrict__ fo,
                                                      float* __restrict__ out) {
    __shared__ unsigned skeys[8192];
    __shared__ int hist[2048];
    __shared__ int wtot[32], woff[32];
    __shared__ unsigned s_bin;
    __shared__ int s_rank;
    __shared__ float rh[1024];
    __shared__ float rf[128];
    __shared__ float terms[25];
    int bx = blockIdx.x;
    int tid = threadIdx.x, lane = tid & 31, wid = tid >> 5;

    if (bx < 100) {
        int a = c_arr[bx];
        int r = c_rank[bx];
        if (a < 6) {
            const float* src = (a < 3 ? real_in : fake_in) + (a % 3);
#pragma unroll
            for (int it = 0; it < 8; it++) {
                int idx = tid + it * 1024;
                skeys[idx] = fkey(src[idx * 3]);
            }
        } else {
            const float* src = &g_knn[0][0][0] + (a - 6) * (NP * 3);
#pragma unroll
            for (int it = 0; it < 8; it++) {
                int idx = tid + it * 1024;
                skeys[idx] = (idx < NP * 3) ? fkey(src[idx]) : 0xFFFFFFFFu;
            }
        }
        __syncthreads();

        unsigned prefix = 0;
#pragma unroll
        for (int level = 0; level < 3; level++) {
            int nb = (level < 2) ? 2048 : 1024;
            int shift = (level == 0) ? 21 : (level == 1 ? 10 : 0);
            for (int bI = tid; bI < nb; bI += 1024) hist[bI] = 0;
            __syncthreads();
#pragma unroll
            for (int it = 0; it < 8; it++) {
                unsigned k = skeys[tid + it * 1024];
                bool ok = (level == 0) ||
                          (level == 1 ? ((k >> 21) == prefix) : ((k >> 10) == prefix));
                unsigned act = __ballot_sync(0xffffffffu, ok);
                if (ok) {
                    unsigned bin = (k >> shift) & (nb - 1);
                    unsigned grp = __match_any_sync(act, bin);
                    int ldr = __ffs(grp) - 1;
                    if (lane == ldr) atomicAdd(&hist[bin], __popc(grp));
                }
            }
            __syncthreads();
            int per = nb >> 10;
            int base = tid * per;
            int local = 0;
            for (int bI = 0; bI < per; bI++) local += hist[base + bI];
            int incl = local;
#pragma unroll
            for (int off = 1; off < 32; off <<= 1) {
                int v = __shfl_up_sync(0xffffffffu, incl, off);
                if (lane >= off) incl += v;
            }
            if (lane == 31) wtot[wid] = incl;
            __syncthreads();
            if (tid < 32) {
                int v = wtot[tid];
                int inc2 = v;
#pragma unroll
                for (int off = 1; off < 32; off <<= 1) {
                    int u = __shfl_up_sync(0xffffffffu, inc2, off);
                    if (tid >= off) inc2 += u;
                }
                woff[tid] = inc2 - v;
            }
            __syncthreads();
            int myExcl = woff[wid] + incl - local;
            if (r >= myExcl && r < myExcl + local) {
                int rr2 = r - myExcl;
                for (int bI = 0; bI < per; bI++) {
                    int h = hist[base + bI];
                    if (rr2 < h) { s_bin = base + bI; s_rank = rr2; break; }
                    rr2 -= h;
                }
            }
            __syncthreads();
            prefix = (prefix << ((level == 2) ? 10 : 11)) | s_bin;
            r = s_rank;
            __syncthreads();
        }
        if (tid == 0) {
            g_sel[a][c_slot[bx]] = unfkey(prefix);
            __threadfence();
            atomicAdd(&g_done, 1);
        }
    } else {
        // -------- final block: select-independent reductions, then spin-wait --------
        rh[tid] = g_hex_partial[tid];
        if (tid < 128) rf[tid] = g_feas_partial[tid];
        __syncthreads();
        for (int off = 512; off; off >>= 1) {
            if (tid < off) rh[tid] += rh[tid + off];
            if (off <= 64 && tid < off) rf[tid] += rf[tid + off];
            __syncthreads();
        }
        if (tid == 0) {
            while (atomicCAS(&g_done, 100, 100) != 100) { }
            __threadfence();
        }
        __syncthreads();
        if (tid < 25) {
            volatile const float* gs = &g_sel[0][0];
            int ar = f_ar[tid], af = f_af[tid], k = f_k[tid];
            double pos = f_q[tid] * (double)(f_n[tid] - 1);
            int lo = (int)pos;
            float fr = (float)(pos - (double)lo);
            float rlo = gs[ar * 14 + 2 * k], rhi = gs[ar * 14 + 2 * k + 1];
            float flo = gs[af * 14 + 2 * k], fhi = gs[af * 14 + 2 * k + 1];
            float qr = rlo + fr * (rhi - rlo);
            float qf = flo + fr * (fhi - flo);
            float d = qf - qr;
            terms[tid] = f_w[tid] * d * d;
        }
        __syncthreads();
        if (tid == 0) {
            float s_sumr = g_sumr[0] + g_sumr[1] + g_sumr[2] + g_sumr[3];
            float loss = 0.0f;
            for (int i = 0; i < 25; i++) loss += terms[i];
            loss += -rh[0] / (float)(BSZ * NP);             // grid order
            loss += rf[0] / ((float)NP * s_sumr);           // feasibility
            float gg = 0.0f;
            for (int i = 0; i < BSZ; i++) {
                float p = fo[i];
                gg += 0.9f * fmaxf(logf(p), -100.0f) + 0.1f * fmaxf(logf(1.0f - p), -100.0f);
            }
            loss += -gg / (float)BSZ;
            out[0] = loss;
        }
    }
}

// ---------------- launch ----------------
extern "C" void kernel_launch(void* const* d_in, const int* in_sizes, int n_in,
                              void* d_out, int out_size) {
    const float* real_in = (const float*)d_in[0];
    const float* fake_in = (const float*)d_in[1];
    const float* fo      = (const float*)d_in[2];
    float* out = (float*)d_out;

    prep_kernel  <<<136, 1024>>>(real_in, fake_in);
    pairs_kernel <<<1536, 256>>>();
    selfin_kernel<<<101, 1024>>>(real_in, fake_in, fo, out);
}